// round 17
// baseline (speedup 1.0000x reference)
#include <cuda_runtime.h>
#include <cuda_fp16.h>
#include <math.h>
#include <stdint.h>

#define SEQ 2048
#define HIDDEN 4096
#define NH 32
#define NKV 8
#define HD 128
#define QD (NH*HD)     // 4096
#define N1 6144        // fused Q|K|V output width

// Scratch (static device globals)
__device__ __half g_hid_h[SEQ*HIDDEN];
__device__ __half g_w1_h[N1*HIDDEN];      // [Wq | Wk | Wv] rows
__device__ __half g_wo_h[HIDDEN*QD];
__device__ __half g_q_h[SEQ*QD];          // normed+roped+scaled Q
__device__ __half g_k_h[SEQ*1024];        // normed+roped K
__device__ __half g_vt[1024*SEQ];         // V^T: [kvh*128+d][token]
__device__ __half g_ctx_h[SEQ*QD];
__device__ float2 g_cs[SEQ*64];           // (cos, sin) per (token, freq)

__device__ __forceinline__ void ldm_x4(uint32_t* r, uint32_t addr) {
    asm volatile("ldmatrix.sync.aligned.m8n8.x4.shared.b16 {%0,%1,%2,%3}, [%4];"
        : "=r"(r[0]), "=r"(r[1]), "=r"(r[2]), "=r"(r[3]) : "r"(addr));
}

__device__ __forceinline__ void mma_h(float* d, const uint32_t* a,
                                      uint32_t b0, uint32_t b1) {
    asm volatile(
        "mma.sync.aligned.m16n8k16.row.col.f32.f16.f16.f32 "
        "{%0,%1,%2,%3},{%4,%5,%6,%7},{%8,%9},{%0,%1,%2,%3};\n"
        : "+f"(d[0]), "+f"(d[1]), "+f"(d[2]), "+f"(d[3])
        : "r"(a[0]), "r"(a[1]), "r"(a[2]), "r"(a[3]), "r"(b0), "r"(b1));
}

__device__ __forceinline__ uint32_t packh2(float x, float y) {
    __half2 h = __floats2half2_rn(x, y);
    return *(uint32_t*)&h;
}

// ---------------------------------------------------------------------------
// Merged fp32->fp16 rounding + cos/sin table (R16 coalesced layout).
// ---------------------------------------------------------------------------
__global__ void __launch_bounds__(256) round_all(
        __half* __restrict__ hid, const float* __restrict__ shid,
        __half* __restrict__ w1,  const float* __restrict__ wq,
        const float* __restrict__ wk, const float* __restrict__ wv,
        __half* __restrict__ wo,  const float* __restrict__ swo,
        float2* __restrict__ cs) {
    long b = blockIdx.x;
    if (b >= 12288) {
        long thr = (b - 12288) * 256 + threadIdx.x;
#pragma unroll
        for (int e = 0; e < 16; ++e) {
            long entry = thr * 16 + e;
            int s = (int)(entry >> 6), f = (int)(entry & 63);
            float invf = exp2f(-19.931568569324174f * ((float)f * (1.0f / 64.0f)));
            float ang = (float)s * invf;
            cs[entry] = make_float2(cosf(ang), sinf(ang));
        }
        return;
    }
    const float* src; __half* dst; long off;
    if (b < 2048)       { src = shid; dst = hid;            off = b; }
    else if (b < 6144)  { src = wq;   dst = w1;             off = b - 2048; }
    else if (b < 7168)  { src = wk;   dst = w1 + 16777216L; off = b - 6144; }
    else if (b < 8192)  { src = wv;   dst = w1 + 20971520L; off = b - 7168; }
    else                { src = swo;  dst = wo;             off = b - 8192; }
    long base = off * 4096;
    int t4 = threadIdx.x * 4;
    float4 v[4];
#pragma unroll
    for (int k = 0; k < 4; ++k)
        v[k] = *(const float4*)(src + base + k * 1024 + t4);
#pragma unroll
    for (int k = 0; k < 4; ++k) {
        __half2 h2[2];
        h2[0] = __floats2half2_rn(v[k].x, v[k].y);
        h2[1] = __floats2half2_rn(v[k].z, v[k].w);
        *(uint2*)(dst + base + k * 1024 + t4) = *(uint2*)h2;
    }
}

// ---------------------------------------------------------------------------
// fp16 GEMM (R12 config) — QKV projection with fused norm/rope/V-T epilogue.
// 128x128 tile, BK=64, 8 warps (warp tile 32x64), 3-stage, 2 CTAs/SM.
// ---------------------------------------------------------------------------
#define SA_H 72
#define STG_OP_BYTES (128*SA_H*2)
#define STAGE_BYTES (2*STG_OP_BYTES)
#define NST 3
#define GEMM_SMEM_BYTES (NST*STAGE_BYTES)

__global__ void __launch_bounds__(256, 2) hgemm(const __half* __restrict__ A,
                                                const __half* __restrict__ B,
                                                int N, int K,
                                                __half* __restrict__ qh,
                                                __half* __restrict__ kh,
                                                __half* __restrict__ vt,
                                                const float* __restrict__ qw,
                                                const float* __restrict__ kw,
                                                const float2* __restrict__ cs) {
    extern __shared__ char smraw[];
    uint32_t sbase = (uint32_t)__cvta_generic_to_shared(smraw);
    const int tid = threadIdx.x;
    const int lane = tid & 31;
    const int warp = tid >> 5;
    const int wm = (warp & 3) * 32;
    const int wn = (warp >> 2) * 64;
    const int m0 = blockIdx.y * 128, n0 = blockIdx.x * 128;

    float acc[2][8][4];
#pragma unroll
    for (int i = 0; i < 2; ++i)
#pragma unroll
        for (int j = 0; j < 8; ++j)
#pragma unroll
            for (int x = 0; x < 4; ++x) acc[i][j][x] = 0.f;

    const int nk = K >> 6;

    auto prefetch = [&](int t) {
        int slot = t % NST;
        uint32_t sa = sbase + slot * STAGE_BYTES;
        uint32_t sb = sa + STG_OP_BYTES;
        int k0 = t << 6;
#pragma unroll
        for (int i = 0; i < 4; ++i) {
            int c = tid + i * 256;
            int row = c >> 3, cc = c & 7;
            uint32_t da = sa + row * 144 + cc * 16;
            const __half* ga = A + (long)(m0 + row) * K + k0 + cc * 8;
            asm volatile("cp.async.cg.shared.global [%0], [%1], 16;\n" :: "r"(da), "l"(ga));
            uint32_t db = sb + row * 144 + cc * 16;
            const __half* gb = B + (long)(n0 + row) * K + k0 + cc * 8;
            asm volatile("cp.async.cg.shared.global [%0], [%1], 16;\n" :: "r"(db), "l"(gb));
        }
        asm volatile("cp.async.commit_group;\n");
    };

    prefetch(0);
    prefetch(1);

    const int aRow = lane & 15;
    const int aCol = 8 * (lane >> 4);
    const int bRow = (lane & 7) + ((lane >> 4) & 1) * 8;
    const int bCol = ((lane >> 3) & 1) * 8;

    for (int t = 0; t < nk; ++t) {
        asm volatile("cp.async.wait_group 1;\n");
        __syncthreads();
        if (t + 2 < nk) prefetch(t + 2);
        else asm volatile("cp.async.commit_group;\n");

        uint32_t sa = sbase + (t % NST) * STAGE_BYTES;
        uint32_t sb = sa + STG_OP_BYTES;

#pragma unroll
        for (int kk = 0; kk < 64; kk += 16) {
            uint32_t a[2][4];
#pragma unroll
            for (int i = 0; i < 2; ++i)
                ldm_x4(a[i], sa + ((wm + i * 16 + aRow) * SA_H + kk + aCol) * 2);
            uint32_t b[8][2];
#pragma unroll
            for (int jp = 0; jp < 4; ++jp) {
                uint32_t bb[4];
                ldm_x4(bb, sb + ((wn + jp * 16 + bRow) * SA_H + kk + bCol) * 2);
                b[2 * jp][0] = bb[0]; b[2 * jp][1] = bb[1];
                b[2 * jp + 1][0] = bb[2]; b[2 * jp + 1][1] = bb[3];
            }
#pragma unroll
            for (int i = 0; i < 2; ++i)
#pragma unroll
                for (int j = 0; j < 8; ++j)
                    mma_h(acc[i][j], a[i], b[j][0], b[j][1]);
        }
    }

    const int r = lane >> 2, c2 = (lane & 3) * 2;

    if (n0 >= 5120) {
        __half* Smh = (__half*)smraw;     // [128 d][136 token-stride]
        __syncthreads();
#pragma unroll
        for (int i = 0; i < 2; ++i)
#pragma unroll
            for (int j = 0; j < 8; ++j) {
                int tok = wm + i * 16 + r;
                int vd = wn + j * 8 + c2;
                Smh[vd * 136 + tok]           = __float2half_rn(acc[i][j][0]);
                Smh[(vd + 1) * 136 + tok]     = __float2half_rn(acc[i][j][1]);
                Smh[vd * 136 + tok + 8]       = __float2half_rn(acc[i][j][2]);
                Smh[(vd + 1) * 136 + tok + 8] = __float2half_rn(acc[i][j][3]);
            }
        __syncthreads();
        const long dcol0 = n0 - 5120;
#pragma unroll
        for (int u = 0; u < 8; ++u) {
            int idx = tid + u * 256;
            int vd = idx >> 4, cc = idx & 15;
            *(uint4*)&vt[(dcol0 + vd) * (long)SEQ + m0 + cc * 8] =
                *(uint4*)&Smh[vd * 136 + cc * 8];
        }
        return;
    }

    // Q or K: RMSNorm over the 128-col head + RoPE
    float* Sm = (float*)smraw;
    float* part = Sm + 128 * 132;
    float* rs = part + 256;

    __syncthreads();

    float psum[4] = {0.f, 0.f, 0.f, 0.f};
#pragma unroll
    for (int i = 0; i < 2; ++i)
#pragma unroll
        for (int j = 0; j < 8; ++j) {
            int row_a = wm + i * 16 + r;
            int col = wn + j * 8 + c2;
            float a0 = acc[i][j][0], a1 = acc[i][j][1];
            float a2 = acc[i][j][2], a3 = acc[i][j][3];
            *(float2*)&Sm[row_a * 132 + col]       = make_float2(a0, a1);
            *(float2*)&Sm[(row_a + 8) * 132 + col] = make_float2(a2, a3);
            psum[i * 2 + 0] += a0 * a0 + a1 * a1;
            psum[i * 2 + 1] += a2 * a2 + a3 * a3;
        }
#pragma unroll
    for (int k = 0; k < 4; ++k) {
        psum[k] += __shfl_xor_sync(0xffffffffu, psum[k], 1);
        psum[k] += __shfl_xor_sync(0xffffffffu, psum[k], 2);
    }
    if ((lane & 3) == 0) {
        int hfl = warp >> 2;
        part[(wm + r) * 2 + hfl]          = psum[0];
        part[(wm + r + 8) * 2 + hfl]      = psum[1];
        part[(wm + 16 + r) * 2 + hfl]     = psum[2];
        part[(wm + 16 + r + 8) * 2 + hfl] = psum[3];
    }
    __syncthreads();
    if (tid < 128)
        rs[tid] = rsqrtf((part[tid * 2] + part[tid * 2 + 1]) * (1.0f / 128.0f) + 1e-6f);
    __syncthreads();

    const bool isQ = (n0 < 4096);
    const float* w = isQ ? qw : kw;
    __half* dst = isQ ? qh : kh;
    const long dstride = isQ ? 4096 : 1024;
    const long dcol0 = isQ ? n0 : (n0 - 4096);
    const float qs = isQ ? 0.08838834764831845f : 1.0f;

#pragma unroll
    for (int u = 0; u < 32; ++u) {
        int flat = tid + u * 256;
        int row = flat >> 6, cp = flat & 63;
        float rr = rs[row];
        float x1 = Sm[row * 132 + cp]      * rr * w[cp];
        float x2 = Sm[row * 132 + cp + 64] * rr * w[cp + 64];
        float2 csv = cs[(long)(m0 + row) * 64 + cp];
        float y1 = (x1 * csv.x - x2 * csv.y) * qs;
        float y2 = (x2 * csv.x + x1 * csv.y) * qs;
        long base = (long)(m0 + row) * dstride + dcol0;
        dst[base + cp]      = __float2half_rn(y1);
        dst[base + cp + 64] = __float2half_rn(y2);
    }
}

// ---------------------------------------------------------------------------
// O-projection GEMM — HIGH-OCCUPANCY variant (3 CTAs/SM = 24 warps/SM).
// Tile 128m x 64n, 8 warps (4m x 2n, warp tile 32x32), BK=64, 2-stage.
// Same K-summation order as hgemm -> bit-identical results.
// ---------------------------------------------------------------------------
#define O_STG_A (128*144)                 // 18432
#define O_STG_B (64*144)                  // 9216
#define O_STAGE (O_STG_A+O_STG_B)         // 27648
#define O_SMEM_BYTES (2*O_STAGE)          // 55296 -> 3 CTAs/SM

__global__ void __launch_bounds__(256, 3) hgemm_o(const __half* __restrict__ A,
                                                  const __half* __restrict__ B,
                                                  float* __restrict__ C,
                                                  int N, int K) {
    extern __shared__ char smraw[];
    uint32_t sbase = (uint32_t)__cvta_generic_to_shared(smraw);
    const int tid = threadIdx.x;
    const int lane = tid & 31;
    const int warp = tid >> 5;
    const int wm = (warp & 3) * 32;
    const int wn = (warp >> 2) * 32;
    const int m0 = blockIdx.y * 128, n0 = blockIdx.x * 64;

    float acc[2][4][4];
#pragma unroll
    for (int i = 0; i < 2; ++i)
#pragma unroll
        for (int j = 0; j < 4; ++j)
#pragma unroll
            for (int x = 0; x < 4; ++x) acc[i][j][x] = 0.f;

    const int nk = K >> 6;

    auto prefetch = [&](int t) {
        int slot = t & 1;
        uint32_t sa = sbase + slot * O_STAGE;
        uint32_t sb = sa + O_STG_A;
        int k0 = t << 6;
#pragma unroll
        for (int i = 0; i < 4; ++i) {               // A: 128 rows x 8 chunks
            int c = tid + i * 256;
            int row = c >> 3, cc = c & 7;
            uint32_t da = sa + row * 144 + cc * 16;
            const __half* ga = A + (long)(m0 + row) * K + k0 + cc * 8;
            asm volatile("cp.async.cg.shared.global [%0], [%1], 16;\n" :: "r"(da), "l"(ga));
        }
#pragma unroll
        for (int i = 0; i < 2; ++i) {               // B: 64 rows x 8 chunks
            int c = tid + i * 256;
            int row = c >> 3, cc = c & 7;
            uint32_t db = sb + row * 144 + cc * 16;
            const __half* gb = B + (long)(n0 + row) * K + k0 + cc * 8;
            asm volatile("cp.async.cg.shared.global [%0], [%1], 16;\n" :: "r"(db), "l"(gb));
        }
        asm volatile("cp.async.commit_group;\n");
    };

    prefetch(0);

    const int aRow = lane & 15;
    const int aCol = 8 * (lane >> 4);
    const int bRow = (lane & 7) + ((lane >> 4) & 1) * 8;
    const int bCol = ((lane >> 3) & 1) * 8;

    for (int t = 0; t < nk; ++t) {
        asm volatile("cp.async.wait_group 0;\n");   // group t complete
        __syncthreads();                             // all reads of other slot done
        if (t + 1 < nk) prefetch(t + 1);             // overlaps compute of t

        uint32_t sa = sbase + (t & 1) * O_STAGE;
        uint32_t sb = sa + O_STG_A;

#pragma unroll
        for (int kk = 0; kk < 64; kk += 16) {
            uint32_t a[2][4];
#pragma unroll
            for (int i = 0; i < 2; ++i)
                ldm_x4(a[i], sa + ((wm + i * 16 + aRow) * SA_H + kk + aCol) * 2);
            uint32_t b[4][2];
#pragma unroll
            for (int jp = 0; jp < 2; ++jp) {
                uint32_t bb[4];
                ldm_x4(bb, sb + ((wn + jp * 16 + bRow) * SA_H + kk + bCol) * 2);
                b[2 * jp][0] = bb[0]; b[2 * jp][1] = bb[1];
                b[2 * jp + 1][0] = bb[2]; b[2 * jp + 1][1] = bb[3];
            }
#pragma unroll
            for (int i = 0; i < 2; ++i)
#pragma unroll
                for (int j = 0; j < 4; ++j)
                    mma_h(acc[i][j], a[i], b[j][0], b[j][1]);
        }
    }

    const int r = lane >> 2, c2 = (lane & 3) * 2;
#pragma unroll
    for (int i = 0; i < 2; ++i)
#pragma unroll
        for (int j = 0; j < 4; ++j) {
            long row0 = m0 + wm + i * 16 + r;
            long col = n0 + wn + j * 8 + c2;
            *(float2*)&C[row0 * N + col]       = make_float2(acc[i][j][0], acc[i][j][1]);
            *(float2*)&C[(row0 + 8) * N + col] = make_float2(acc[i][j][2], acc[i][j][3]);
        }
}

// ---------------------------------------------------------------------------
// Flash attention (R12 exact): fp16 mma, Q tile 128, KV tile 128 double-
// buffered, Q fragments register-resident, P reused as A-fragment directly.
// ---------------------------------------------------------------------------
#define AQ 128
#define AK 128
#define QSH 136
#define OFF_QS 0
#define OFF_KS 17408
#define OFF_VT (17408 + 2*17408)
#define ATTN_SMEM_BYTES ((OFF_VT + 2*17408)*2)   // 174080

__global__ void __launch_bounds__(256) attn_mma(const __half* __restrict__ gq,
                                                const __half* __restrict__ gk,
                                                const __half* __restrict__ gvt,
                                                __half* __restrict__ gctx) {
    extern __shared__ __half smh[];
    uint32_t sb = (uint32_t)__cvta_generic_to_shared(smh);
    const uint32_t qs_a = sb + OFF_QS * 2;

    const int tid = threadIdx.x;
    const int lane = tid & 31;
    const int warp = tid >> 5;
    const int r = lane >> 2, c4 = lane & 3;
    const int qblk = gridDim.x - 1 - blockIdx.x;
    const int q0 = qblk * AQ;
    const int h = blockIdx.y;
    const int kvh = h >> 2;
    const int qr = warp * 16;

    const int aRow = lane & 15;
    const int aCol = 8 * (lane >> 4);
    const int bRow = (lane & 7) + ((lane >> 4) & 1) * 8;
    const int bCol = ((lane >> 3) & 1) * 8;

    const int ntiles = qblk + 1;

    auto fill = [&](int t) {
        int slot = t & 1;
        int k0 = t * AK;
        uint32_t ka = sb + (OFF_KS + slot * 17408) * 2;
        uint32_t va = sb + (OFF_VT + slot * 17408) * 2;
#pragma unroll
        for (int i = 0; i < 8; ++i) {
            int idx = tid + i * 256;
            int row = idx >> 4, cc = idx & 15;
            uint32_t dst = ka + row * 272 + cc * 16;
            const __half* src = gk + (long)(k0 + row) * 1024 + kvh * HD + cc * 8;
            asm volatile("cp.async.cg.shared.global [%0], [%1], 16;\n" :: "r"(dst), "l"(src));
        }
#pragma unroll
        for (int i = 0; i < 8; ++i) {
            int idx = tid + i * 256;
            int row = idx >> 4, cc = idx & 15;
            uint32_t dst = va + row * 272 + cc * 16;
            const __half* src = gvt + (long)(kvh * HD + row) * SEQ + k0 + cc * 8;
            asm volatile("cp.async.cg.shared.global [%0], [%1], 16;\n" :: "r"(dst), "l"(src));
        }
        asm volatile("cp.async.commit_group;\n");
    };

    fill(0);

#pragma unroll
    for (int i = 0; i < 8; ++i) {
        int idx = tid + i * 256;
        int row = idx >> 4, cc = idx & 15;
        *(uint4*)(smh + OFF_QS + row * QSH + cc * 8) =
            *(const uint4*)(gq + (long)(q0 + row) * QD + h * HD + cc * 8);
    }
    __syncthreads();
    uint32_t qf[8][4];
#pragma unroll
    for (int kk = 0; kk < 8; ++kk)
        ldm_x4(qf[kk], qs_a + ((qr + aRow) * QSH + kk * 16 + aCol) * 2);

    float m_run[2] = {-1e30f, -1e30f};
    float l_run[2] = {0.f, 0.f};
    float o[16][4];
#pragma unroll
    for (int f = 0; f < 16; ++f)
#pragma unroll
        for (int x = 0; x < 4; ++x) o[f][x] = 0.f;

    const int row0 = q0 + qr + r;
    const int row1 = row0 + 8;

    for (int t = 0; t < ntiles; ++t) {
        const int k0 = t * AK;
        __syncthreads();
        if (t + 1 < ntiles) {
            fill(t + 1);
            asm volatile("cp.async.wait_group 1;\n");
        } else {
            asm volatile("cp.async.wait_group 0;\n");
        }
        __syncthreads();

        const uint32_t ks_a = sb + (OFF_KS + (t & 1) * 17408) * 2;
        const uint32_t vt_a = sb + (OFF_VT + (t & 1) * 17408) * 2;

        float s[16][4];
#pragma unroll
        for (int j = 0; j < 16; ++j)
#pragma unroll
            for (int x = 0; x < 4; ++x) s[j][x] = 0.f;

#pragma unroll
        for (int kk = 0; kk < 8; ++kk) {
#pragma unroll
            for (int jp = 0; jp < 8; ++jp) {
                uint32_t bb[4];
                ldm_x4(bb, ks_a + ((jp * 16 + bRow) * QSH + kk * 16 + bCol) * 2);
                mma_h(s[2 * jp],     qf[kk], bb[0], bb[1]);
                mma_h(s[2 * jp + 1], qf[kk], bb[2], bb[3]);
            }
        }

        const bool dg = (t == ntiles - 1);
        float mx0 = -1e30f, mx1 = -1e30f;
#pragma unroll
        for (int j = 0; j < 16; ++j) {
            int col = k0 + j * 8 + 2 * c4;
            if (dg) {
                if (col     > row0) s[j][0] = -1e30f;
                if (col + 1 > row0) s[j][1] = -1e30f;
                if (col     > row1) s[j][2] = -1e30f;
                if (col + 1 > row1) s[j][3] = -1e30f;
            }
            mx0 = fmaxf(mx0, fmaxf(s[j][0], s[j][1]));
            mx1 = fmaxf(mx1, fmaxf(s[j][2], s[j][3]));
        }
        mx0 = fmaxf(mx0, __shfl_xor_sync(0xffffffffu, mx0, 1));
        mx0 = fmaxf(mx0, __shfl_xor_sync(0xffffffffu, mx0, 2));
        mx1 = fmaxf(mx1, __shfl_xor_sync(0xffffffffu, mx1, 1));
        mx1 = fmaxf(mx1, __shfl_xor_sync(0xffffffffu, mx1, 2));

        float mn0 = fmaxf(m_run[0], mx0);
        float mn1 = fmaxf(m_run[1], mx1);
        float cr0 = __expf(m_run[0] - mn0);
        float cr1 = __expf(m_run[1] - mn1);
        m_run[0] = mn0; m_run[1] = mn1;

        float sum0 = 0.f, sum1 = 0.f;
#pragma unroll
        for (int j = 0; j < 16; ++j) {
            s[j][0] = __expf(s[j][0] - mn0);
            s[j][1] = __expf(s[j][1] - mn0);
            s[j][2] = __expf(s[j][2] - mn1);
            s[j][3] = __expf(s[j][3] - mn1);
            sum0 += s[j][0] + s[j][1];
            sum1 += s[j][2] + s[j][3];
        }
        sum0 += __shfl_xor_sync(0xffffffffu, sum0, 1);
        sum0 += __shfl_xor_sync(0xffffffffu, sum0, 2);
        sum1 += __shfl_xor_sync(0xffffffffu, sum1, 1);
        sum1 += __shfl_xor_sync(0xffffffffu, sum1, 2);
        l_run[0] = l_run[0] * cr0 + sum0;
        l_run[1] = l_run[1] * cr1 + sum1;

#pragma unroll
        for (int f = 0; f < 16; ++f) {
            o[f][0] *= cr0; o[f][1] *= cr0;
            o[f][2] *= cr1; o[f][3] *= cr1;
        }

#pragma unroll
        for (int kt = 0; kt < 8; ++kt) {
            uint32_t a[4];
            a[0] = packh2(s[2 * kt][0],     s[2 * kt][1]);
            a[1] = packh2(s[2 * kt][2],     s[2 * kt][3]);
            a[2] = packh2(s[2 * kt + 1][0], s[2 * kt + 1][1]);
            a[3] = packh2(s[2 * kt + 1][2], s[2 * kt + 1][3]);
#pragma unroll
            for (int fp = 0; fp < 8; ++fp) {
                uint32_t bb[4];
                ldm_x4(bb, vt_a + ((fp * 16 + bRow) * QSH + kt * 16 + bCol) * 2);
                mma_h(o[2 * fp],     a, bb[0], bb[1]);
                mma_h(o[2 * fp + 1], a, bb[2], bb[3]);
            }
        }
    }

    float inv0 = 1.f / l_run[0];
    float inv1 = 1.f / l_run[1];
#pragma unroll
    for (int f = 0; f < 16; ++f) {
        long base0 = (long)row0 * QD + h * HD + f * 8 + 2 * c4;
        *(__half2*)&gctx[base0] =
            __floats2half2_rn(o[f][0] * inv0, o[f][1] * inv0);
        *(__half2*)&gctx[base0 + 8L * QD] =
            __floats2half2_rn(o[f][2] * inv1, o[f][3] * inv1);
    }
}

// ---------------------------------------------------------------------------
extern "C" void kernel_launch(void* const* d_in, const int* in_sizes, int n_in,
                              void* d_out, int out_size) {
    const float* hidden = (const float*)d_in[0];
    const float* Wq = (const float*)d_in[3];
    const float* Wk = (const float*)d_in[4];
    const float* Wv = (const float*)d_in[5];
    const float* Wo = (const float*)d_in[6];
    const float* qw = (const float*)d_in[7];
    const float* kw = (const float*)d_in[8];
    float* out = (float*)d_out;

    __half *phid, *pw1, *pwo, *pqh, *pkh, *pvt, *pctx;
    float2* pcs;
    cudaGetSymbolAddress((void**)&phid, g_hid_h);
    cudaGetSymbolAddress((void**)&pw1, g_w1_h);
    cudaGetSymbolAddress((void**)&pwo, g_wo_h);
    cudaGetSymbolAddress((void**)&pqh, g_q_h);
    cudaGetSymbolAddress((void**)&pkh, g_k_h);
    cudaGetSymbolAddress((void**)&pvt, g_vt);
    cudaGetSymbolAddress((void**)&pctx, g_ctx_h);
    cudaGetSymbolAddress((void**)&pcs, g_cs);

    round_all<<<12320, 256>>>(phid, hidden, pw1, Wq, Wk, Wv, pwo, Wo, pcs);

    cudaFuncSetAttribute(hgemm, cudaFuncAttributeMaxDynamicSharedMemorySize,
                         GEMM_SMEM_BYTES);

    // Fused QKV projection with norm/rope/V-transpose epilogue (R12 config)
    hgemm<<<dim3(N1 / 128, SEQ / 128), 256, GEMM_SMEM_BYTES>>>(
        phid, pw1, N1, HIDDEN, pqh, pkh, pvt, qw, kw, pcs);

    cudaFuncSetAttribute(attn_mma, cudaFuncAttributeMaxDynamicSharedMemorySize,
                         ATTN_SMEM_BYTES);
    attn_mma<<<dim3(SEQ / AQ, NH), 256, ATTN_SMEM_BYTES>>>(pqh, pkh, pvt, pctx);

    // Output projection -> d_out (high-occupancy 3-CTA/SM variant)
    cudaFuncSetAttribute(hgemm_o, cudaFuncAttributeMaxDynamicSharedMemorySize,
                         O_SMEM_BYTES);
    hgemm_o<<<dim3(HIDDEN / 64, SEQ / 128), 256, O_SMEM_BYTES>>>(
        pctx, pwo, out, HIDDEN, HIDDEN);
}